// round 8
// baseline (speedup 1.0000x reference)
#include <cuda_runtime.h>
#include <cstdint>

// ---------------------------------------------------------------------------
// GlobalFusion: sparse->dense scatter fusion, DIM=96, C=24.
// Outputs (f32, concatenated in tuple order):
//   updated_mask   [96^3]            off 0
//   current_volume [96^3 * 24]       off 884736
//   global_volume  [96^3 * 24]       off 22118400
//   target_volume  [96^3]            off 43352064
//   valid          [300000]          off 44236800
//   valid_target   [200000]          off 44536800
//   near_mask      [300000]          off 44736800
//
// R8: same serial pipeline as R7 (measured best), resolve widened from
// 4 to 8 independent load chains per thread (4 cells x {cur,glb}).
// ---------------------------------------------------------------------------

#define DIMV   96
#define NCELLS (96 * 96 * 96)   // 884736
#define NC4    6                // 24 floats = 6 float4
#define QCELLS (NCELLS / 4)     // 221184
#define N_CUR  150000
#define N_GLB  300000
#define N_TGT  100000
#define N_GTGT 200000

#define OFF_UPD 0
#define OFF_CV  884736
#define OFF_GV  22118400
#define OFF_TV  43352064
#define OFF_VAL 44236800
#define OFF_VT  44536800
#define OFF_NR  44736800

// Scratch (static device globals; no allocation allowed)
__device__ int           g_cur_win[NCELLS];
__device__ int           g_glb_win[NCELLS];
__device__ int           g_tgt_win[NCELLS];
__device__ unsigned char g_valid_vol[NCELLS];
__device__ unsigned char g_occ[NCELLS];

// --------------------------------------------------------------------------
// 1) reset scratch (int4-vectorized)
// --------------------------------------------------------------------------
__global__ void k_init()
{
    int i = blockIdx.x * blockDim.x + threadIdx.x;           // NCELLS/4 threads
    if (i < NCELLS / 4) {
        int4 m1 = make_int4(-1, -1, -1, -1);
        reinterpret_cast<int4*>(g_cur_win)[i] = m1;
        reinterpret_cast<int4*>(g_glb_win)[i] = m1;
        reinterpret_cast<int4*>(g_tgt_win)[i] = m1;
        reinterpret_cast<uint*>(g_valid_vol)[i] = 0u;
        reinterpret_cast<uint*>(g_occ)[i] = 0u;
    }
}

// --------------------------------------------------------------------------
// 2) fused scatter: current-fragment rows + both target scatters.
//    JAX sequential-scatter semantics (last duplicate row wins) -> atomicMax
//    on row index; current-fragment target rows get priority N_GTGT+j so
//    they always beat the global target rows (torch cat order).
// --------------------------------------------------------------------------
__global__ void k_scat1(const int* __restrict__ cc,
                        const int* __restrict__ grid_mask,
                        const int* __restrict__ occupancy,
                        const int* __restrict__ gct,
                        const int* __restrict__ ct,
                        const int* __restrict__ org,
                        float* __restrict__ out_vt)
{
    int i = blockIdx.x * blockDim.x + threadIdx.x;

    if (i < N_CUR) {
        int x = cc[3 * i + 0];
        int y = cc[3 * i + 1];
        int z = cc[3 * i + 2];
        int cell = (x * DIMV + y) * DIMV + z;
        if (grid_mask[i]) g_valid_vol[cell] = 1;
        if (occupancy[i]) g_occ[cell] = 1;
        atomicMax(&g_cur_win[cell], i);
        return;
    }
    int t = i - N_CUR;
    if (t < N_GTGT) {
        int ox = __ldg(&org[0]), oy = __ldg(&org[1]), oz = __ldg(&org[2]);
        int x = gct[3 * t + 0] - ox;
        int y = gct[3 * t + 1] - oy;
        int z = gct[3 * t + 2] - oz;
        bool inb = ((unsigned)x < DIMV) && ((unsigned)y < DIMV) && ((unsigned)z < DIMV);
        out_vt[t] = inb ? 1.0f : 0.0f;
        if (inb) atomicMax(&g_tgt_win[(x * DIMV + y) * DIMV + z], t);
        return;
    }
    int j = t - N_GTGT;
    if (j < N_TGT) {
        int x = ct[3 * j + 0];
        int y = ct[3 * j + 1];
        int z = ct[3 * j + 2];
        atomicMax(&g_tgt_win[(x * DIMV + y) * DIMV + z], N_GTGT + j);
    }
}

// --------------------------------------------------------------------------
// 3) global-fragment rows: bounds + visibility gather, valid/near, glb winner
// --------------------------------------------------------------------------
__global__ void k_glb(const int* __restrict__ gc,
                      const int* __restrict__ org,
                      float* __restrict__ out_valid,
                      float* __restrict__ out_near)
{
    int i = blockIdx.x * blockDim.x + threadIdx.x;
    if (i >= N_GLB) return;
    int ox = __ldg(&org[0]), oy = __ldg(&org[1]), oz = __ldg(&org[2]);
    int x = gc[3 * i + 0] - ox;
    int y = gc[3 * i + 1] - oy;
    int z = gc[3 * i + 2] - oz;
    bool inb = ((unsigned)x < DIMV) && ((unsigned)y < DIMV) && ((unsigned)z < DIMV);
    bool valid = false;
    if (inb) {
        int cell = (x * DIMV + y) * DIMV + z;
        valid = (g_valid_vol[cell] != 0);
        if (valid) atomicMax(&g_glb_win[cell], i);
    }
    out_valid[i] = valid ? 1.0f : 0.0f;
    out_near[i]  = (inb && !valid) ? 1.0f : 0.0f;
}

// --------------------------------------------------------------------------
// 4) monolithic resolve, 8 independent chains per thread.
//    Thread t handles slot q of cells c, c+Q, c+2Q, c+3Q (Q = NCELLS/4) for
//    BOTH volumes: 8 winner loads issued back-to-back, then 8 independent
//    random gathers, then 8 fully-coalesced float4 stores.
//    q==0 lanes additionally emit updated_mask + target_volume (4 cells).
// --------------------------------------------------------------------------
__global__ void k_resolve(const float4* __restrict__ cur_vals,   // [N_CUR*6]
                          const float4* __restrict__ glb_vals,   // [N_GLB*6]
                          const float*  __restrict__ g_tsdf,     // [N_GTGT]
                          const float*  __restrict__ c_tsdf,     // [N_TGT]
                          float* __restrict__ out)
{
    int tid = blockIdx.x * blockDim.x + threadIdx.x;
    if (tid >= QCELLS * NC4) return;
    int cell0 = tid / NC4;
    int q     = tid - cell0 * NC4;

    int cells[4], tids[4];
#pragma unroll
    for (int k = 0; k < 4; k++) {
        cells[k] = cell0 + k * QCELLS;
        tids[k]  = tid   + k * QCELLS * NC4;
    }

    // ---- 8 independent winner loads ----
    int wc[4], wg[4];
#pragma unroll
    for (int k = 0; k < 4; k++) wc[k] = g_cur_win[cells[k]];
#pragma unroll
    for (int k = 0; k < 4; k++) wg[k] = g_glb_win[cells[k]];

    float4 zero = make_float4(0.f, 0.f, 0.f, 0.f);

    // ---- 8 independent gathers ----
    float4 cv[4], gv[4];
#pragma unroll
    for (int k = 0; k < 4; k++)
        cv[k] = (wc[k] >= 0) ? __ldg(&cur_vals[wc[k] * NC4 + q]) : zero;
#pragma unroll
    for (int k = 0; k < 4; k++)
        gv[k] = (wg[k] >= 0) ? __ldg(&glb_vals[wg[k] * NC4 + q]) : zero;

    // ---- coalesced stores ----
    float4* out_cv = reinterpret_cast<float4*>(out + OFF_CV);
    float4* out_gv = reinterpret_cast<float4*>(out + OFF_GV);
#pragma unroll
    for (int k = 0; k < 4; k++) out_cv[tids[k]] = cv[k];
#pragma unroll
    for (int k = 0; k < 4; k++) out_gv[tids[k]] = gv[k];

    if (q == 0) {
        int wt[4];
        unsigned char oc[4];
#pragma unroll
        for (int k = 0; k < 4; k++) wt[k] = g_tgt_win[cells[k]];
#pragma unroll
        for (int k = 0; k < 4; k++) oc[k] = g_occ[cells[k]];

#pragma unroll
        for (int k = 0; k < 4; k++)
            out[OFF_UPD + cells[k]] = (wg[k] >= 0 || oc[k]) ? 1.0f : 0.0f;

#pragma unroll
        for (int k = 0; k < 4; k++) {
            float tv = 1.0f;
            if (wt[k] >= 0)
                tv = (wt[k] < N_GTGT) ? __ldg(&g_tsdf[wt[k]])
                                      : __ldg(&c_tsdf[wt[k] - N_GTGT]);
            out[OFF_TV + cells[k]] = tv;
        }
    }
}

// ---------------------------------------------------------------------------
extern "C" void kernel_launch(void* const* d_in, const int* in_sizes, int n_in,
                              void* d_out, int out_size)
{
    const int*   current_coords     = (const int*)  d_in[0];
    const float* current_values     = (const float*)d_in[1];
    const int*   global_coords      = (const int*)  d_in[2];
    const float* global_value       = (const float*)d_in[3];
    const int*   coords_tgt_global  = (const int*)  d_in[4];
    const float* tsdf_target        = (const float*)d_in[5];
    const int*   global_coords_tgt  = (const int*)  d_in[6];
    const float* global_tsdf_target = (const float*)d_in[7];
    const int*   relative_origin    = (const int*)  d_in[8];
    const int*   grid_mask          = (const int*)  d_in[9];
    const int*   occupancy          = (const int*)  d_in[10];

    float* out = (float*)d_out;

    const int B = 256;
    const int N_SCAT1 = N_CUR + N_GTGT + N_TGT;

    k_init<<<(NCELLS / 4 + B - 1) / B, B>>>();
    k_scat1<<<(N_SCAT1 + B - 1) / B, B>>>(current_coords, grid_mask, occupancy,
                                          global_coords_tgt, coords_tgt_global,
                                          relative_origin, out + OFF_VT);
    k_glb<<<(N_GLB + B - 1) / B, B>>>(global_coords, relative_origin,
                                      out + OFF_VAL, out + OFF_NR);
    k_resolve<<<(QCELLS * NC4 + B - 1) / B, B>>>(
        (const float4*)current_values, (const float4*)global_value,
        global_tsdf_target, tsdf_target, out);
}

// round 14
// speedup vs baseline: 1.1364x; 1.1364x over previous
#include <cuda_runtime.h>
#include <cstdint>

// ---------------------------------------------------------------------------
// GlobalFusion: sparse->dense scatter fusion, DIM=96, C=24.
// Outputs (f32, concatenated in tuple order):
//   updated_mask   [96^3]            off 0
//   current_volume [96^3 * 24]       off 884736
//   global_volume  [96^3 * 24]       off 22118400
//   target_volume  [96^3]            off 43352064
//   valid          [300000]          off 44236800
//   valid_target   [200000]          off 44536800
//   near_mask      [300000]          off 44736800
//
// R10 (= R9 resubmit; R9 bench was a container infra failure):
// R8's 8-chain resolve + __launch_bounds__(256,2) so ptxas gets a 128-reg
// budget instead of spilling 8 float4s to local (R8's regression cause).
// ---------------------------------------------------------------------------

#define DIMV   96
#define NCELLS (96 * 96 * 96)   // 884736
#define NC4    6                // 24 floats = 6 float4
#define QCELLS (NCELLS / 4)     // 221184
#define N_CUR  150000
#define N_GLB  300000
#define N_TGT  100000
#define N_GTGT 200000

#define OFF_UPD 0
#define OFF_CV  884736
#define OFF_GV  22118400
#define OFF_TV  43352064
#define OFF_VAL 44236800
#define OFF_VT  44536800
#define OFF_NR  44736800

// Scratch (static device globals; no allocation allowed)
__device__ int           g_cur_win[NCELLS];
__device__ int           g_glb_win[NCELLS];
__device__ int           g_tgt_win[NCELLS];
__device__ unsigned char g_valid_vol[NCELLS];
__device__ unsigned char g_occ[NCELLS];

// --------------------------------------------------------------------------
// 1) reset scratch (int4-vectorized)
// --------------------------------------------------------------------------
__global__ void k_init()
{
    int i = blockIdx.x * blockDim.x + threadIdx.x;           // NCELLS/4 threads
    if (i < NCELLS / 4) {
        int4 m1 = make_int4(-1, -1, -1, -1);
        reinterpret_cast<int4*>(g_cur_win)[i] = m1;
        reinterpret_cast<int4*>(g_glb_win)[i] = m1;
        reinterpret_cast<int4*>(g_tgt_win)[i] = m1;
        reinterpret_cast<uint*>(g_valid_vol)[i] = 0u;
        reinterpret_cast<uint*>(g_occ)[i] = 0u;
    }
}

// --------------------------------------------------------------------------
// 2) fused scatter: current-fragment rows + both target scatters.
//    JAX sequential-scatter semantics (last duplicate row wins) -> atomicMax
//    on row index; current-fragment target rows get priority N_GTGT+j so
//    they always beat the global target rows (torch cat order).
// --------------------------------------------------------------------------
__global__ void k_scat1(const int* __restrict__ cc,
                        const int* __restrict__ grid_mask,
                        const int* __restrict__ occupancy,
                        const int* __restrict__ gct,
                        const int* __restrict__ ct,
                        const int* __restrict__ org,
                        float* __restrict__ out_vt)
{
    int i = blockIdx.x * blockDim.x + threadIdx.x;

    if (i < N_CUR) {
        int x = cc[3 * i + 0];
        int y = cc[3 * i + 1];
        int z = cc[3 * i + 2];
        int cell = (x * DIMV + y) * DIMV + z;
        if (grid_mask[i]) g_valid_vol[cell] = 1;
        if (occupancy[i]) g_occ[cell] = 1;
        atomicMax(&g_cur_win[cell], i);
        return;
    }
    int t = i - N_CUR;
    if (t < N_GTGT) {
        int ox = __ldg(&org[0]), oy = __ldg(&org[1]), oz = __ldg(&org[2]);
        int x = gct[3 * t + 0] - ox;
        int y = gct[3 * t + 1] - oy;
        int z = gct[3 * t + 2] - oz;
        bool inb = ((unsigned)x < DIMV) && ((unsigned)y < DIMV) && ((unsigned)z < DIMV);
        out_vt[t] = inb ? 1.0f : 0.0f;
        if (inb) atomicMax(&g_tgt_win[(x * DIMV + y) * DIMV + z], t);
        return;
    }
    int j = t - N_GTGT;
    if (j < N_TGT) {
        int x = ct[3 * j + 0];
        int y = ct[3 * j + 1];
        int z = ct[3 * j + 2];
        atomicMax(&g_tgt_win[(x * DIMV + y) * DIMV + z], N_GTGT + j);
    }
}

// --------------------------------------------------------------------------
// 3) global-fragment rows: bounds + visibility gather, valid/near, glb winner
// --------------------------------------------------------------------------
__global__ void k_glb(const int* __restrict__ gc,
                      const int* __restrict__ org,
                      float* __restrict__ out_valid,
                      float* __restrict__ out_near)
{
    int i = blockIdx.x * blockDim.x + threadIdx.x;
    if (i >= N_GLB) return;
    int ox = __ldg(&org[0]), oy = __ldg(&org[1]), oz = __ldg(&org[2]);
    int x = gc[3 * i + 0] - ox;
    int y = gc[3 * i + 1] - oy;
    int z = gc[3 * i + 2] - oz;
    bool inb = ((unsigned)x < DIMV) && ((unsigned)y < DIMV) && ((unsigned)z < DIMV);
    bool valid = false;
    if (inb) {
        int cell = (x * DIMV + y) * DIMV + z;
        valid = (g_valid_vol[cell] != 0);
        if (valid) atomicMax(&g_glb_win[cell], i);
    }
    out_valid[i] = valid ? 1.0f : 0.0f;
    out_near[i]  = (inb && !valid) ? 1.0f : 0.0f;
}

// --------------------------------------------------------------------------
// 4) monolithic resolve, 8 independent chains per thread, 128-reg budget.
//    Thread t handles slot q of cells c, c+Q, c+2Q, c+3Q (Q = NCELLS/4) for
//    BOTH volumes: 8 winner loads issued back-to-back, then 8 independent
//    random gathers (all live simultaneously -> needs ~64 regs, hence the
//    __launch_bounds__(256,2) budget), then 8 fully-coalesced float4 stores.
//    q==0 lanes additionally emit updated_mask + target_volume (4 cells).
// --------------------------------------------------------------------------
__global__ void __launch_bounds__(256, 2)
k_resolve(const float4* __restrict__ cur_vals,   // [N_CUR*6]
          const float4* __restrict__ glb_vals,   // [N_GLB*6]
          const float*  __restrict__ g_tsdf,     // [N_GTGT]
          const float*  __restrict__ c_tsdf,     // [N_TGT]
          float* __restrict__ out)
{
    int tid = blockIdx.x * blockDim.x + threadIdx.x;
    if (tid >= QCELLS * NC4) return;
    int cell0 = tid / NC4;
    int q     = tid - cell0 * NC4;

    int cells[4], tids[4];
#pragma unroll
    for (int k = 0; k < 4; k++) {
        cells[k] = cell0 + k * QCELLS;
        tids[k]  = tid   + k * QCELLS * NC4;
    }

    // ---- 8 independent winner loads ----
    int wc[4], wg[4];
#pragma unroll
    for (int k = 0; k < 4; k++) wc[k] = g_cur_win[cells[k]];
#pragma unroll
    for (int k = 0; k < 4; k++) wg[k] = g_glb_win[cells[k]];

    float4 zero = make_float4(0.f, 0.f, 0.f, 0.f);

    // ---- 8 independent gathers, all in flight together ----
    float4 cv[4], gv[4];
#pragma unroll
    for (int k = 0; k < 4; k++)
        cv[k] = (wc[k] >= 0) ? __ldg(&cur_vals[wc[k] * NC4 + q]) : zero;
#pragma unroll
    for (int k = 0; k < 4; k++)
        gv[k] = (wg[k] >= 0) ? __ldg(&glb_vals[wg[k] * NC4 + q]) : zero;

    // ---- coalesced stores ----
    float4* out_cv = reinterpret_cast<float4*>(out + OFF_CV);
    float4* out_gv = reinterpret_cast<float4*>(out + OFF_GV);
#pragma unroll
    for (int k = 0; k < 4; k++) out_cv[tids[k]] = cv[k];
#pragma unroll
    for (int k = 0; k < 4; k++) out_gv[tids[k]] = gv[k];

    if (q == 0) {
        int wt[4];
        unsigned char oc[4];
#pragma unroll
        for (int k = 0; k < 4; k++) wt[k] = g_tgt_win[cells[k]];
#pragma unroll
        for (int k = 0; k < 4; k++) oc[k] = g_occ[cells[k]];

#pragma unroll
        for (int k = 0; k < 4; k++)
            out[OFF_UPD + cells[k]] = (wg[k] >= 0 || oc[k]) ? 1.0f : 0.0f;

#pragma unroll
        for (int k = 0; k < 4; k++) {
            float tv = 1.0f;
            if (wt[k] >= 0)
                tv = (wt[k] < N_GTGT) ? __ldg(&g_tsdf[wt[k]])
                                      : __ldg(&c_tsdf[wt[k] - N_GTGT]);
            out[OFF_TV + cells[k]] = tv;
        }
    }
}

// ---------------------------------------------------------------------------
extern "C" void kernel_launch(void* const* d_in, const int* in_sizes, int n_in,
                              void* d_out, int out_size)
{
    const int*   current_coords     = (const int*)  d_in[0];
    const float* current_values     = (const float*)d_in[1];
    const int*   global_coords      = (const int*)  d_in[2];
    const float* global_value       = (const float*)d_in[3];
    const int*   coords_tgt_global  = (const int*)  d_in[4];
    const float* tsdf_target        = (const float*)d_in[5];
    const int*   global_coords_tgt  = (const int*)  d_in[6];
    const float* global_tsdf_target = (const float*)d_in[7];
    const int*   relative_origin    = (const int*)  d_in[8];
    const int*   grid_mask          = (const int*)  d_in[9];
    const int*   occupancy          = (const int*)  d_in[10];

    float* out = (float*)d_out;

    const int B = 256;
    const int N_SCAT1 = N_CUR + N_GTGT + N_TGT;

    k_init<<<(NCELLS / 4 + B - 1) / B, B>>>();
    k_scat1<<<(N_SCAT1 + B - 1) / B, B>>>(current_coords, grid_mask, occupancy,
                                          global_coords_tgt, coords_tgt_global,
                                          relative_origin, out + OFF_VT);
    k_glb<<<(N_GLB + B - 1) / B, B>>>(global_coords, relative_origin,
                                      out + OFF_VAL, out + OFF_NR);
    k_resolve<<<(QCELLS * NC4 + B - 1) / B, B>>>(
        (const float4*)current_values, (const float4*)global_value,
        global_tsdf_target, tsdf_target, out);
}